// round 13
// baseline (speedup 1.0000x reference)
#include <cuda_runtime.h>

// SymmetryControl (square-symmetry branch), B=16,C=96,H=96,W=96.
// Single-kernel butterfly-orbit + packed f32x2 + per-block SMEM gate hoist:
//   - threads 0..4 of each block compute sigmoid(s) for the block's batch
//     into SMEM (each 192-thread block = 32 rows = one batch)
//   - every thread issues its 8 LDG.128 BEFORE the barrier, so the
//     __syncthreads cost hides under the loads
//   - orbit pair (p, 5-p) of a row on adjacent lanes; each thread holds ONE
//     orbit (4 f4 of p=x*w + 4 f4 of w as packed f32x2 halves), pulls partner
//     values via shfl.bfly(xor=1) packed REVERSED at shuffle time
//   - rolling flip window: per-m flip180 slot == previous m's flip90 slot
// Output elem i = 4t+c:
//   shifts: f4 (t+18)%24, (t+12)%24, (t+6)%24, component c
//   flips:  f4 (5-t)%24 (partner slot (4-m)&3) and (11-t)%24 (slot (1-m)&3),
//           component 3-c (reversed)

#define W4 24
#define NT 192
#define ROWS_PER_BLOCK 32   // NT/6

typedef unsigned long long ull;

__device__ __forceinline__ ull pk2(float lo, float hi) {
    ull r; asm("mov.b64 %0, {%1, %2};" : "=l"(r) : "f"(lo), "f"(hi)); return r;
}
__device__ __forceinline__ void upk2(float& lo, float& hi, ull v) {
    asm("mov.b64 {%0, %1}, %2;" : "=f"(lo), "=f"(hi) : "l"(v));
}
__device__ __forceinline__ ull fma2(ull a, ull b, ull c) {
    ull d; asm("fma.rn.f32x2 %0, %1, %2, %3;" : "=l"(d) : "l"(a), "l"(b), "l"(c));
    return d;
}
__device__ __forceinline__ ull mul2(ull a, ull b) {
    ull d; asm("mul.rn.f32x2 %0, %1, %2;" : "=l"(d) : "l"(a), "l"(b));
    return d;
}
// Shuffle a packed pair from lane^1, halves swapped (component-reversed).
__device__ __forceinline__ ull shfl_rev(ull v) {
    float lo, hi; upk2(lo, hi, v);
    const float a = __shfl_xor_sync(0xffffffffu, hi, 1);
    const float b = __shfl_xor_sync(0xffffffffu, lo, 1);
    return pk2(a, b);
}

__global__ __launch_bounds__(NT, 5)
void symmetry_control_bfly4(const float4* __restrict__ x4,
                            const float*  __restrict__ s,
                            const float4* __restrict__ w4,
                            float4* __restrict__ out4,
                            int rows_per_batch /* C*H = 9216 */)
{
    __shared__ float sg[5];

    // lanes (2q, 2q+1) hold orbits (p, 5-p) of one row.
    const unsigned tid   = blockIdx.x * NT + threadIdx.x;
    const unsigned gpair = tid >> 1;
    const unsigned side  = tid & 1;
    const unsigned row   = gpair / 3;
    const unsigned p     = gpair % 3;
    const unsigned o     = side ? (5 - p) : p;   // my orbit id (0..5)
    const unsigned base  = row * W4 + o;         // fits 32-bit

    // Gates: one sigmoid set per block (block = 32 rows = single batch).
    if (threadIdx.x < 5) {
        const unsigned b = (blockIdx.x * ROWS_PER_BLOCK) / (unsigned)rows_per_batch;
        sg[threadIdx.x] = 1.0f / (1.0f + __expf(-s[b * 5 + threadIdx.x]));
    }

    // My orbit: 8 independent streaming LDG.128, in flight across the barrier.
    ull Pl[4], Ph[4], Wl[4], Wh[4];
#pragma unroll
    for (int k = 0; k < 4; k++) {
        const float4 xv = __ldcs(&x4[base + 6 * k]);
        const float4 wv = __ldcs(&w4[base + 6 * k]);
        Wl[k] = pk2(wv.x, wv.y);
        Wh[k] = pk2(wv.z, wv.w);
        Pl[k] = mul2(pk2(xv.x, xv.y), Wl[k]);
        Ph[k] = mul2(pk2(xv.z, xv.w), Wh[k]);
    }

    __syncthreads();
    const float g0 = sg[0], g1 = sg[1], g2 = sg[2], g3 = sg[3], g4 = sg[4];
    const ull G0 = pk2(g0, g0), G1 = pk2(g1, g1), G2 = pk2(g2, g2),
              G3 = pk2(g3, g3), G4 = pk2(g4, g4);

    // Rolling flip-operand window.
    ull qaL, qaH, vaL, vaH;   // flip90 operands (slot (4-m)&3)
    ull qbL, qbH, vbL, vbH;   // flip180 operands (slot (1-m)&3)

#pragma unroll
    for (int m = 0; m < 4; m++) {
        const int m1 = (m + 1) & 3;      // +6  f4 (270deg, gate g2)
        const int m2 = (m + 2) & 3;      // +12 f4 (180deg, gate g1)
        const int m3 = (m + 3) & 3;      // +18 f4 (90deg,  gate g0)
        const int kf90 = (4 - m) & 3;    // flip90 slot in partner orbit

        if (m == 0) {
            qaL = shfl_rev(Ph[0]); qaH = shfl_rev(Pl[0]);
            vaL = shfl_rev(Wh[0]); vaH = shfl_rev(Wl[0]);
            qbL = shfl_rev(Ph[1]); qbH = shfl_rev(Pl[1]);
            vbL = shfl_rev(Wh[1]); vbH = shfl_rev(Wl[1]);
        } else {
            qbL = qaL; qbH = qaH; vbL = vaL; vbH = vaH;
            qaL = shfl_rev(Ph[kf90]); qaH = shfl_rev(Pl[kf90]);
            vaL = shfl_rev(Wh[kf90]); vaH = shfl_rev(Wl[kf90]);
        }

        ull nL = Pl[m];
        nL = fma2(G0, Pl[m3], nL); nL = fma2(G1, Pl[m2], nL);
        nL = fma2(G2, Pl[m1], nL);
        nL = fma2(G3, qaL, nL);    nL = fma2(G4, qbL, nL);
        ull nH = Ph[m];
        nH = fma2(G0, Ph[m3], nH); nH = fma2(G1, Ph[m2], nH);
        nH = fma2(G2, Ph[m1], nH);
        nH = fma2(G3, qaH, nH);    nH = fma2(G4, qbH, nH);

        ull dL = Wl[m];
        dL = fma2(G0, Wl[m3], dL); dL = fma2(G1, Wl[m2], dL);
        dL = fma2(G2, Wl[m1], dL);
        dL = fma2(G3, vaL, dL);    dL = fma2(G4, vbL, dL);
        ull dH = Wh[m];
        dH = fma2(G0, Wh[m3], dH); dH = fma2(G1, Wh[m2], dH);
        dH = fma2(G2, Wh[m1], dH);
        dH = fma2(G3, vaH, dH);    dH = fma2(G4, vbH, dH);

        float n0, n1, n2, n3, d0, d1, d2, d3;
        upk2(n0, n1, nL); upk2(n2, n3, nH);
        upk2(d0, d1, dL); upk2(d2, d3, dH);

        float4 oo;
        oo.x = __fdividef(n0, d0);
        oo.y = __fdividef(n1, d1);
        oo.z = __fdividef(n2, d2);
        oo.w = __fdividef(n3, d3);

        __stcs(&out4[base + 6 * m], oo);
    }
}

extern "C" void kernel_launch(void* const* d_in, const int* in_sizes, int n_in,
                              void* d_out, int out_size)
{
    const float4* x4 = (const float4*)d_in[0];
    const float*  s  = (const float*)d_in[1];
    const float4* w4 = (const float4*)d_in[2];
    float4* out4 = (float4*)d_out;

    const long long total = in_sizes[0];          // B*C*H*W = 14,155,776
    const int B = in_sizes[1] / 5;                // 16
    const long long rows = total / 96;            // 147,456
    const int rows_per_batch = (int)(rows / B);   // 9216

    const long long nthreads = rows * 6;          // 884,736
    const long long nblocks  = nthreads / NT;     // 4608 (exact)
    symmetry_control_bfly4<<<(unsigned)nblocks, NT>>>(x4, s, w4, out4, rows_per_batch);
}

// round 14
// speedup vs baseline: 1.0099x; 1.0099x over previous
#include <cuda_runtime.h>

// SymmetryControl (square-symmetry branch), B=16,C=96,H=96,W=96.
// Butterfly-orbit + packed f32x2, barrier-free single kernel.
// Gates via WARP broadcast (no smem, no __syncthreads):
//   - block = 192 threads = 32 rows = one batch -> gate set uniform per block
//   - lanes<5 load s early; all lanes run sigmoid after the LDG burst
//     (branch-free); 5 shfl broadcasts deliver g0..g4
// Dataflow (proven R9-R12): orbit pair (p,5-p) of a row on adjacent lanes;
// each thread holds ONE orbit (4 f4 of p=x*w + 4 f4 of w, packed f32x2
// halves), pulls partner values via shfl.bfly(xor=1) packed REVERSED;
// rolling flip window (per-m flip180 slot == previous m's flip90 slot).
// Output elem i = 4t+c:
//   shifts: f4 (t+18)%24, (t+12)%24, (t+6)%24, component c
//   flips:  f4 (5-t)%24 (partner slot (4-m)&3) and (11-t)%24 (slot (1-m)&3),
//           component 3-c (reversed)

#define W4 24
#define NT 192
#define ROWS_PER_BLOCK 32   // NT/6

typedef unsigned long long ull;

__device__ __forceinline__ ull pk2(float lo, float hi) {
    ull r; asm("mov.b64 %0, {%1, %2};" : "=l"(r) : "f"(lo), "f"(hi)); return r;
}
__device__ __forceinline__ void upk2(float& lo, float& hi, ull v) {
    asm("mov.b64 {%0, %1}, %2;" : "=f"(lo), "=f"(hi) : "l"(v));
}
__device__ __forceinline__ ull fma2(ull a, ull b, ull c) {
    ull d; asm("fma.rn.f32x2 %0, %1, %2, %3;" : "=l"(d) : "l"(a), "l"(b), "l"(c));
    return d;
}
__device__ __forceinline__ ull mul2(ull a, ull b) {
    ull d; asm("mul.rn.f32x2 %0, %1, %2;" : "=l"(d) : "l"(a), "l"(b));
    return d;
}
// Shuffle a packed pair from lane^1, halves swapped (component-reversed).
__device__ __forceinline__ ull shfl_rev(ull v) {
    float lo, hi; upk2(lo, hi, v);
    const float a = __shfl_xor_sync(0xffffffffu, hi, 1);
    const float b = __shfl_xor_sync(0xffffffffu, lo, 1);
    return pk2(a, b);
}

__global__ __launch_bounds__(NT, 5)
void symmetry_control_bfly5(const float4* __restrict__ x4,
                            const float*  __restrict__ s,
                            const float4* __restrict__ w4,
                            float4* __restrict__ out4,
                            int rows_per_batch /* C*H = 9216 */)
{
    // lanes (2q, 2q+1) hold orbits (p, 5-p) of one row.
    const unsigned tid   = blockIdx.x * NT + threadIdx.x;
    const unsigned gpair = tid >> 1;
    const unsigned side  = tid & 1;
    const unsigned row   = gpair / 3;
    const unsigned p     = gpair % 3;
    const unsigned o     = side ? (5 - p) : p;   // my orbit id (0..5)
    const unsigned base  = row * W4 + o;         // fits 32-bit

    // Gate inputs: batch uniform per block; lanes<5 load s early (latency
    // hides under the LDG burst below).
    const unsigned b = (blockIdx.x * ROWS_PER_BLOCK) / (unsigned)rows_per_batch;
    const unsigned lane = threadIdx.x & 31;
    const float sv = (lane < 5) ? s[b * 5 + lane] : 0.0f;

    // My orbit: 8 independent streaming LDG.128, packed halves.
    ull Pl[4], Ph[4], Wl[4], Wh[4];
#pragma unroll
    for (int k = 0; k < 4; k++) {
        const float4 xv = __ldcs(&x4[base + 6 * k]);
        const float4 wv = __ldcs(&w4[base + 6 * k]);
        Wl[k] = pk2(wv.x, wv.y);
        Wh[k] = pk2(wv.z, wv.w);
        Pl[k] = mul2(pk2(xv.x, xv.y), Wl[k]);
        Ph[k] = mul2(pk2(xv.z, xv.w), Wh[k]);
    }

    // Sigmoid on all lanes (branch-free; only lanes<5 carry real data),
    // then warp broadcast.
    const float gv = 1.0f / (1.0f + __expf(-sv));
    const float g0 = __shfl_sync(0xffffffffu, gv, 0);
    const float g1 = __shfl_sync(0xffffffffu, gv, 1);
    const float g2 = __shfl_sync(0xffffffffu, gv, 2);
    const float g3 = __shfl_sync(0xffffffffu, gv, 3);
    const float g4 = __shfl_sync(0xffffffffu, gv, 4);
    const ull G0 = pk2(g0, g0), G1 = pk2(g1, g1), G2 = pk2(g2, g2),
              G3 = pk2(g3, g3), G4 = pk2(g4, g4);

    // Rolling flip-operand window.
    ull qaL, qaH, vaL, vaH;   // flip90 operands (slot (4-m)&3)
    ull qbL, qbH, vbL, vbH;   // flip180 operands (slot (1-m)&3)

#pragma unroll
    for (int m = 0; m < 4; m++) {
        const int m1 = (m + 1) & 3;      // +6  f4 (270deg, gate g2)
        const int m2 = (m + 2) & 3;      // +12 f4 (180deg, gate g1)
        const int m3 = (m + 3) & 3;      // +18 f4 (90deg,  gate g0)
        const int kf90 = (4 - m) & 3;    // flip90 slot in partner orbit

        if (m == 0) {
            qaL = shfl_rev(Ph[0]); qaH = shfl_rev(Pl[0]);
            vaL = shfl_rev(Wh[0]); vaH = shfl_rev(Wl[0]);
            qbL = shfl_rev(Ph[1]); qbH = shfl_rev(Pl[1]);
            vbL = shfl_rev(Wh[1]); vbH = shfl_rev(Wl[1]);
        } else {
            qbL = qaL; qbH = qaH; vbL = vaL; vbH = vaH;
            qaL = shfl_rev(Ph[kf90]); qaH = shfl_rev(Pl[kf90]);
            vaL = shfl_rev(Wh[kf90]); vaH = shfl_rev(Wl[kf90]);
        }

        ull nL = Pl[m];
        nL = fma2(G0, Pl[m3], nL); nL = fma2(G1, Pl[m2], nL);
        nL = fma2(G2, Pl[m1], nL);
        nL = fma2(G3, qaL, nL);    nL = fma2(G4, qbL, nL);
        ull nH = Ph[m];
        nH = fma2(G0, Ph[m3], nH); nH = fma2(G1, Ph[m2], nH);
        nH = fma2(G2, Ph[m1], nH);
        nH = fma2(G3, qaH, nH);    nH = fma2(G4, qbH, nH);

        ull dL = Wl[m];
        dL = fma2(G0, Wl[m3], dL); dL = fma2(G1, Wl[m2], dL);
        dL = fma2(G2, Wl[m1], dL);
        dL = fma2(G3, vaL, dL);    dL = fma2(G4, vbL, dL);
        ull dH = Wh[m];
        dH = fma2(G0, Wh[m3], dH); dH = fma2(G1, Wh[m2], dH);
        dH = fma2(G2, Wh[m1], dH);
        dH = fma2(G3, vaH, dH);    dH = fma2(G4, vbH, dH);

        float n0, n1, n2, n3, d0, d1, d2, d3;
        upk2(n0, n1, nL); upk2(n2, n3, nH);
        upk2(d0, d1, dL); upk2(d2, d3, dH);

        float4 oo;
        oo.x = __fdividef(n0, d0);
        oo.y = __fdividef(n1, d1);
        oo.z = __fdividef(n2, d2);
        oo.w = __fdividef(n3, d3);

        __stcs(&out4[base + 6 * m], oo);
    }
}

extern "C" void kernel_launch(void* const* d_in, const int* in_sizes, int n_in,
                              void* d_out, int out_size)
{
    const float4* x4 = (const float4*)d_in[0];
    const float*  s  = (const float*)d_in[1];
    const float4* w4 = (const float4*)d_in[2];
    float4* out4 = (float4*)d_out;

    const long long total = in_sizes[0];          // B*C*H*W = 14,155,776
    const int B = in_sizes[1] / 5;                // 16
    const long long rows = total / 96;            // 147,456
    const int rows_per_batch = (int)(rows / B);   // 9216

    const long long nthreads = rows * 6;          // 884,736
    const long long nblocks  = nthreads / NT;     // 4608 (exact)
    symmetry_control_bfly5<<<(unsigned)nblocks, NT>>>(x4, s, w4, out4, rows_per_batch);
}

// round 15
// speedup vs baseline: 1.1604x; 1.1490x over previous
#include <cuda_runtime.h>

// SymmetryControl (square-symmetry branch), B=16,C=96,H=96,W=96.
// Butterfly-orbit + packed f32x2, barrier-free, warp-broadcast gates.
//   - NT=128, __launch_bounds__(128,7): best-benched occupancy config (R11)
//   - gates: lanes<5 load s early (latency under LDG burst), all lanes run
//     one sigmoid, 5 shfl broadcasts deliver g0..g4; batch id from the
//     warp's first pair (warps never straddle a batch: boundaries fall on
//     gpair multiples of 27648, multiple of 16)
//   - orbit pair (p,5-p) of a row on adjacent lanes; each thread holds ONE
//     orbit (4 f4 of p=x*w + 4 f4 of w, packed f32x2 halves), pulls partner
//     values via shfl.bfly(xor=1) packed REVERSED at shuffle time
//   - rolling flip window: per-m flip180 slot == previous m's flip90 slot
// Output elem i = 4t+c:
//   shifts: f4 (t+18)%24, (t+12)%24, (t+6)%24, component c
//   flips:  f4 (5-t)%24 (partner slot (4-m)&3) and (11-t)%24 (slot (1-m)&3),
//           component 3-c (reversed)

#define W4 24
#define NT 128

typedef unsigned long long ull;

__device__ __forceinline__ ull pk2(float lo, float hi) {
    ull r; asm("mov.b64 %0, {%1, %2};" : "=l"(r) : "f"(lo), "f"(hi)); return r;
}
__device__ __forceinline__ void upk2(float& lo, float& hi, ull v) {
    asm("mov.b64 {%0, %1}, %2;" : "=f"(lo), "=f"(hi) : "l"(v));
}
__device__ __forceinline__ ull fma2(ull a, ull b, ull c) {
    ull d; asm("fma.rn.f32x2 %0, %1, %2, %3;" : "=l"(d) : "l"(a), "l"(b), "l"(c));
    return d;
}
__device__ __forceinline__ ull mul2(ull a, ull b) {
    ull d; asm("mul.rn.f32x2 %0, %1, %2;" : "=l"(d) : "l"(a), "l"(b));
    return d;
}
// Shuffle a packed pair from lane^1, halves swapped (component-reversed).
__device__ __forceinline__ ull shfl_rev(ull v) {
    float lo, hi; upk2(lo, hi, v);
    const float a = __shfl_xor_sync(0xffffffffu, hi, 1);
    const float b = __shfl_xor_sync(0xffffffffu, lo, 1);
    return pk2(a, b);
}

__global__ __launch_bounds__(NT, 7)
void symmetry_control_bfly6(const float4* __restrict__ x4,
                            const float*  __restrict__ s,
                            const float4* __restrict__ w4,
                            float4* __restrict__ out4,
                            int rows_per_batch /* C*H = 9216 */)
{
    // lanes (2q, 2q+1) hold orbits (p, 5-p) of one row.
    const unsigned tid   = blockIdx.x * NT + threadIdx.x;
    const unsigned gpair = tid >> 1;
    const unsigned side  = tid & 1;
    const unsigned row   = gpair / 3;
    const unsigned p     = gpair % 3;
    const unsigned o     = side ? (5 - p) : p;   // my orbit id (0..5)
    const unsigned base  = row * W4 + o;         // fits 32-bit

    // Warp-uniform batch id from the warp's first pair (never straddles).
    const unsigned lane  = threadIdx.x & 31;
    const unsigned wg0   = (blockIdx.x * NT + (threadIdx.x & ~31u)) >> 1;
    const unsigned b     = (wg0 / 3) / (unsigned)rows_per_batch;
    const float sv = (lane < 5) ? s[b * 5 + lane] : 0.0f;

    // My orbit: 8 independent streaming LDG.128, packed halves.
    ull Pl[4], Ph[4], Wl[4], Wh[4];
#pragma unroll
    for (int k = 0; k < 4; k++) {
        const float4 xv = __ldcs(&x4[base + 6 * k]);
        const float4 wv = __ldcs(&w4[base + 6 * k]);
        Wl[k] = pk2(wv.x, wv.y);
        Wh[k] = pk2(wv.z, wv.w);
        Pl[k] = mul2(pk2(xv.x, xv.y), Wl[k]);
        Ph[k] = mul2(pk2(xv.z, xv.w), Wh[k]);
    }

    // Sigmoid on all lanes (branch-free), then warp broadcast.
    const float gv = 1.0f / (1.0f + __expf(-sv));
    const float g0 = __shfl_sync(0xffffffffu, gv, 0);
    const float g1 = __shfl_sync(0xffffffffu, gv, 1);
    const float g2 = __shfl_sync(0xffffffffu, gv, 2);
    const float g3 = __shfl_sync(0xffffffffu, gv, 3);
    const float g4 = __shfl_sync(0xffffffffu, gv, 4);
    const ull G0 = pk2(g0, g0), G1 = pk2(g1, g1), G2 = pk2(g2, g2),
              G3 = pk2(g3, g3), G4 = pk2(g4, g4);

    // Rolling flip-operand window.
    ull qaL, qaH, vaL, vaH;   // flip90 operands (slot (4-m)&3)
    ull qbL, qbH, vbL, vbH;   // flip180 operands (slot (1-m)&3)

#pragma unroll
    for (int m = 0; m < 4; m++) {
        const int m1 = (m + 1) & 3;      // +6  f4 (270deg, gate g2)
        const int m2 = (m + 2) & 3;      // +12 f4 (180deg, gate g1)
        const int m3 = (m + 3) & 3;      // +18 f4 (90deg,  gate g0)
        const int kf90 = (4 - m) & 3;    // flip90 slot in partner orbit

        if (m == 0) {
            qaL = shfl_rev(Ph[0]); qaH = shfl_rev(Pl[0]);
            vaL = shfl_rev(Wh[0]); vaH = shfl_rev(Wl[0]);
            qbL = shfl_rev(Ph[1]); qbH = shfl_rev(Pl[1]);
            vbL = shfl_rev(Wh[1]); vbH = shfl_rev(Wl[1]);
        } else {
            qbL = qaL; qbH = qaH; vbL = vaL; vbH = vaH;
            qaL = shfl_rev(Ph[kf90]); qaH = shfl_rev(Pl[kf90]);
            vaL = shfl_rev(Wh[kf90]); vaH = shfl_rev(Wl[kf90]);
        }

        ull nL = Pl[m];
        nL = fma2(G0, Pl[m3], nL); nL = fma2(G1, Pl[m2], nL);
        nL = fma2(G2, Pl[m1], nL);
        nL = fma2(G3, qaL, nL);    nL = fma2(G4, qbL, nL);
        ull nH = Ph[m];
        nH = fma2(G0, Ph[m3], nH); nH = fma2(G1, Ph[m2], nH);
        nH = fma2(G2, Ph[m1], nH);
        nH = fma2(G3, qaH, nH);    nH = fma2(G4, qbH, nH);

        ull dL = Wl[m];
        dL = fma2(G0, Wl[m3], dL); dL = fma2(G1, Wl[m2], dL);
        dL = fma2(G2, Wl[m1], dL);
        dL = fma2(G3, vaL, dL);    dL = fma2(G4, vbL, dL);
        ull dH = Wh[m];
        dH = fma2(G0, Wh[m3], dH); dH = fma2(G1, Wh[m2], dH);
        dH = fma2(G2, Wh[m1], dH);
        dH = fma2(G3, vaH, dH);    dH = fma2(G4, vbH, dH);

        float n0, n1, n2, n3, d0, d1, d2, d3;
        upk2(n0, n1, nL); upk2(n2, n3, nH);
        upk2(d0, d1, dL); upk2(d2, d3, dH);

        float4 oo;
        oo.x = __fdividef(n0, d0);
        oo.y = __fdividef(n1, d1);
        oo.z = __fdividef(n2, d2);
        oo.w = __fdividef(n3, d3);

        __stcs(&out4[base + 6 * m], oo);
    }
}

extern "C" void kernel_launch(void* const* d_in, const int* in_sizes, int n_in,
                              void* d_out, int out_size)
{
    const float4* x4 = (const float4*)d_in[0];
    const float*  s  = (const float*)d_in[1];
    const float4* w4 = (const float4*)d_in[2];
    float4* out4 = (float4*)d_out;

    const long long total = in_sizes[0];          // B*C*H*W = 14,155,776
    const int B = in_sizes[1] / 5;                // 16
    const long long rows = total / 96;            // 147,456
    const int rows_per_batch = (int)(rows / B);   // 9216

    const long long nthreads = rows * 6;          // 884,736
    const long long nblocks  = nthreads / NT;     // 6912 (exact)
    symmetry_control_bfly6<<<(unsigned)nblocks, NT>>>(x4, s, w4, out4, rows_per_batch);
}